// round 6
// baseline (speedup 1.0000x reference)
#include <cuda_runtime.h>
#include <cuda_bf16.h>
#include <cstdint>

// MaxAggregator: out[n, :] = max over s of features[neighbor_idx[n, s], :]
// N = 100000 nodes, S = 10 samples, D = 256 features (fp32).
//
// R6: 8 column tiles x 32 cols. Gathered slice per tile = 12.8 MB (L2-resident,
// even two tiles' slices coexist at wave boundaries). Each row-slice = exactly
// one 128B line -> perfect sector efficiency. 8 threads/node -> 4 nodes/warp,
// halving idx-load issue and address ALU per node. 32-bit offset math.

#define NUM_SAMPLE 10
#define D_FEAT 256
#define N_TILES 8
#define TILE_CHUNKS 8                     // float4 chunks per tile (32 cols)
#define ROW_BYTES (D_FEAT * 4)            // 1024 B per feature row
#define THREADS_PER_NODE TILE_CHUNKS      // 8

__device__ __forceinline__ float4 ldg_nc(const float* base, uint32_t off) {
    float4 v;
    asm("ld.global.nc.v4.f32 {%0,%1,%2,%3}, [%4];"
        : "=f"(v.x), "=f"(v.y), "=f"(v.z), "=f"(v.w)
        : "l"((const char*)base + off));
    return v;
}

__device__ __forceinline__ void stg_cs(float* base, uint32_t off, float4 v) {
    asm volatile("st.global.cs.v4.f32 [%0], {%1,%2,%3,%4};"
        :: "l"((char*)base + off), "f"(v.x), "f"(v.y), "f"(v.z), "f"(v.w)
        : "memory");
}

__global__ void __launch_bounds__(256, 4) max_agg_kernel(
    const int* __restrict__ neighbor_idx,   // [N, 10]
    const float* __restrict__ features,     // [U, 256]
    float* __restrict__ out,                // [N, 256]
    int n_nodes, int blocks_per_tile)
{
    int tile = blockIdx.x / blocks_per_tile;          // 0..7
    int bid_in_tile = blockIdx.x - tile * blocks_per_tile;

    long long t = (long long)bid_in_tile * blockDim.x + threadIdx.x;
    int node  = (int)(t >> 3);                        // t / 8
    int chunk = (int)(t & 7);                         // t % 8
    if (node >= n_nodes) return;

    // byte offset of this thread's float4 within a feature row (0..1008)
    uint32_t cbytes = (uint32_t)(tile * TILE_CHUNKS + chunk) * 16u;

    // idx row = 40 bytes, 8B-aligned -> 5x int2, same address across the
    // node's 8 threads (broadcast; 4 nodes per warp -> halved issue).
    const int2* idx2 = (const int2*)(neighbor_idx + (long long)node * NUM_SAMPLE);
    int2 p0 = __ldg(idx2 + 0);
    int2 p1 = __ldg(idx2 + 1);
    int2 p2 = __ldg(idx2 + 2);
    int2 p3 = __ldg(idx2 + 3);
    int2 p4 = __ldg(idx2 + 4);

    // 32-bit byte offsets (table = 102.4 MB < 4 GB)
    uint32_t o0 = (uint32_t)p0.x * ROW_BYTES + cbytes;
    uint32_t o1 = (uint32_t)p0.y * ROW_BYTES + cbytes;
    uint32_t o2 = (uint32_t)p1.x * ROW_BYTES + cbytes;
    uint32_t o3 = (uint32_t)p1.y * ROW_BYTES + cbytes;
    uint32_t o4 = (uint32_t)p2.x * ROW_BYTES + cbytes;
    uint32_t o5 = (uint32_t)p2.y * ROW_BYTES + cbytes;
    uint32_t o6 = (uint32_t)p3.x * ROW_BYTES + cbytes;
    uint32_t o7 = (uint32_t)p3.y * ROW_BYTES + cbytes;
    uint32_t o8 = (uint32_t)p4.x * ROW_BYTES + cbytes;
    uint32_t o9 = (uint32_t)p4.y * ROW_BYTES + cbytes;

    // 10 independent gathered loads -> MLP=10; slice is L2-resident.
    float4 v0 = ldg_nc(features, o0);
    float4 v1 = ldg_nc(features, o1);
    float4 v2 = ldg_nc(features, o2);
    float4 v3 = ldg_nc(features, o3);
    float4 v4 = ldg_nc(features, o4);
    float4 v5 = ldg_nc(features, o5);
    float4 v6 = ldg_nc(features, o6);
    float4 v7 = ldg_nc(features, o7);
    float4 v8 = ldg_nc(features, o8);
    float4 v9 = ldg_nc(features, o9);

    float4 m;
    m.x = fmaxf(v0.x, v1.x); m.y = fmaxf(v0.y, v1.y);
    m.z = fmaxf(v0.z, v1.z); m.w = fmaxf(v0.w, v1.w);
    m.x = fmaxf(m.x, v2.x);  m.y = fmaxf(m.y, v2.y);
    m.z = fmaxf(m.z, v2.z);  m.w = fmaxf(m.w, v2.w);
    m.x = fmaxf(m.x, v3.x);  m.y = fmaxf(m.y, v3.y);
    m.z = fmaxf(m.z, v3.z);  m.w = fmaxf(m.w, v3.w);
    m.x = fmaxf(m.x, v4.x);  m.y = fmaxf(m.y, v4.y);
    m.z = fmaxf(m.z, v4.z);  m.w = fmaxf(m.w, v4.w);
    m.x = fmaxf(m.x, v5.x);  m.y = fmaxf(m.y, v5.y);
    m.z = fmaxf(m.z, v5.z);  m.w = fmaxf(m.w, v5.w);
    m.x = fmaxf(m.x, v6.x);  m.y = fmaxf(m.y, v6.y);
    m.z = fmaxf(m.z, v6.z);  m.w = fmaxf(m.w, v6.w);
    m.x = fmaxf(m.x, v7.x);  m.y = fmaxf(m.y, v7.y);
    m.z = fmaxf(m.z, v7.z);  m.w = fmaxf(m.w, v7.w);
    m.x = fmaxf(m.x, v8.x);  m.y = fmaxf(m.y, v8.y);
    m.z = fmaxf(m.z, v8.z);  m.w = fmaxf(m.w, v8.w);
    m.x = fmaxf(m.x, v9.x);  m.y = fmaxf(m.y, v9.y);
    m.z = fmaxf(m.z, v9.z);  m.w = fmaxf(m.w, v9.w);

    uint32_t oout = (uint32_t)node * ROW_BYTES + cbytes;
    stg_cs(out, oout, m);
}

extern "C" void kernel_launch(void* const* d_in, const int* in_sizes, int n_in,
                              void* d_out, int out_size) {
    const int* neighbor_idx = (const int*)d_in[0];       // [N, 10] int32
    const float* features   = (const float*)d_in[1];     // [U, 256] fp32
    float* out = (float*)d_out;

    int n_nodes = in_sizes[0] / NUM_SAMPLE;              // 100000

    long long threads_per_tile = (long long)n_nodes * THREADS_PER_NODE;  // 800K
    int block = 256;
    int blocks_per_tile = (int)((threads_per_tile + block - 1) / block); // 3125
    int grid = blocks_per_tile * N_TILES;                                // 25000

    max_agg_kernel<<<grid, block>>>(neighbor_idx, features, out,
                                    n_nodes, blocks_per_tile);
}

// round 7
// speedup vs baseline: 1.0843x; 1.0843x over previous
#include <cuda_runtime.h>
#include <cuda_bf16.h>
#include <cstdint>

// MaxAggregator: out[n, :] = max over s of features[neighbor_idx[n, s], :]
// N = 100000 nodes, S = 10 samples, D = 256 features (fp32).
//
// R7: keep R6's 8 tiles x 32 cols (12.8 MB L2-resident slice, one 128B line
// per gathered row-slice), but revert the R6 occupancy killers: no
// launch_bounds min-blocks cap, plain __ldg/store codegen (32-40 regs,
// occ back to ~84%). 8 threads/node, 32-bit byte-offset address math.

#define NUM_SAMPLE 10
#define D_FEAT 256
#define N_TILES 8
#define TILE_CHUNKS 8                     // float4 chunks per tile (32 cols)
#define ROW_BYTES (D_FEAT * 4)            // 1024 B per feature row
#define THREADS_PER_NODE TILE_CHUNKS      // 8

__global__ void __launch_bounds__(256) max_agg_kernel(
    const int* __restrict__ neighbor_idx,   // [N, 10]
    const float* __restrict__ features,     // [U, 256]
    float* __restrict__ out,                // [N, 256]
    int n_nodes, int blocks_per_tile)
{
    int tile = blockIdx.x / blocks_per_tile;          // 0..7
    int bid_in_tile = blockIdx.x - tile * blocks_per_tile;

    int t = bid_in_tile * blockDim.x + threadIdx.x;   // < 800000, fits int
    int node  = t >> 3;                               // t / 8
    int chunk = t & 7;                                // t % 8
    if (node >= n_nodes) return;

    // byte offset of this thread's float4 within a feature row
    uint32_t cbytes = (uint32_t)(tile * TILE_CHUNKS + chunk) * 16u;

    // idx row = 40 bytes, 8B-aligned -> 5x int2; same address across the
    // node's 8 threads (broadcast), 4 nodes per warp.
    const int2* idx2 = (const int2*)(neighbor_idx + (long long)node * NUM_SAMPLE);
    int2 p0 = __ldg(idx2 + 0);
    int2 p1 = __ldg(idx2 + 1);
    int2 p2 = __ldg(idx2 + 2);
    int2 p3 = __ldg(idx2 + 3);
    int2 p4 = __ldg(idx2 + 4);

    const char* fbase = (const char*)features;

    // 32-bit byte offsets (table = 102.4 MB < 4 GB)
    const float4* a0 = (const float4*)(fbase + ((uint32_t)p0.x * ROW_BYTES + cbytes));
    const float4* a1 = (const float4*)(fbase + ((uint32_t)p0.y * ROW_BYTES + cbytes));
    const float4* a2 = (const float4*)(fbase + ((uint32_t)p1.x * ROW_BYTES + cbytes));
    const float4* a3 = (const float4*)(fbase + ((uint32_t)p1.y * ROW_BYTES + cbytes));
    const float4* a4 = (const float4*)(fbase + ((uint32_t)p2.x * ROW_BYTES + cbytes));
    const float4* a5 = (const float4*)(fbase + ((uint32_t)p2.y * ROW_BYTES + cbytes));
    const float4* a6 = (const float4*)(fbase + ((uint32_t)p3.x * ROW_BYTES + cbytes));
    const float4* a7 = (const float4*)(fbase + ((uint32_t)p3.y * ROW_BYTES + cbytes));
    const float4* a8 = (const float4*)(fbase + ((uint32_t)p4.x * ROW_BYTES + cbytes));
    const float4* a9 = (const float4*)(fbase + ((uint32_t)p4.y * ROW_BYTES + cbytes));

    // 10 independent gathered loads -> MLP=10; slice is L2-resident.
    float4 v0 = __ldg(a0);
    float4 v1 = __ldg(a1);
    float4 v2 = __ldg(a2);
    float4 v3 = __ldg(a3);
    float4 v4 = __ldg(a4);
    float4 v5 = __ldg(a5);
    float4 v6 = __ldg(a6);
    float4 v7 = __ldg(a7);
    float4 v8 = __ldg(a8);
    float4 v9 = __ldg(a9);

    float4 m;
    m.x = fmaxf(v0.x, v1.x); m.y = fmaxf(v0.y, v1.y);
    m.z = fmaxf(v0.z, v1.z); m.w = fmaxf(v0.w, v1.w);
    m.x = fmaxf(m.x, v2.x);  m.y = fmaxf(m.y, v2.y);
    m.z = fmaxf(m.z, v2.z);  m.w = fmaxf(m.w, v2.w);
    m.x = fmaxf(m.x, v3.x);  m.y = fmaxf(m.y, v3.y);
    m.z = fmaxf(m.z, v3.z);  m.w = fmaxf(m.w, v3.w);
    m.x = fmaxf(m.x, v4.x);  m.y = fmaxf(m.y, v4.y);
    m.z = fmaxf(m.z, v4.z);  m.w = fmaxf(m.w, v4.w);
    m.x = fmaxf(m.x, v5.x);  m.y = fmaxf(m.y, v5.y);
    m.z = fmaxf(m.z, v5.z);  m.w = fmaxf(m.w, v5.w);
    m.x = fmaxf(m.x, v6.x);  m.y = fmaxf(m.y, v6.y);
    m.z = fmaxf(m.z, v6.z);  m.w = fmaxf(m.w, v6.w);
    m.x = fmaxf(m.x, v7.x);  m.y = fmaxf(m.y, v7.y);
    m.z = fmaxf(m.z, v7.z);  m.w = fmaxf(m.w, v7.w);
    m.x = fmaxf(m.x, v8.x);  m.y = fmaxf(m.y, v8.y);
    m.z = fmaxf(m.z, v8.z);  m.w = fmaxf(m.w, v8.w);
    m.x = fmaxf(m.x, v9.x);  m.y = fmaxf(m.y, v9.y);
    m.z = fmaxf(m.z, v9.z);  m.w = fmaxf(m.w, v9.w);

    *(float4*)((char*)out + ((uint32_t)node * ROW_BYTES + cbytes)) = m;
}

extern "C" void kernel_launch(void* const* d_in, const int* in_sizes, int n_in,
                              void* d_out, int out_size) {
    const int* neighbor_idx = (const int*)d_in[0];       // [N, 10] int32
    const float* features   = (const float*)d_in[1];     // [U, 256] fp32
    float* out = (float*)d_out;

    int n_nodes = in_sizes[0] / NUM_SAMPLE;              // 100000

    long long threads_per_tile = (long long)n_nodes * THREADS_PER_NODE;  // 800K
    int block = 256;
    int blocks_per_tile = (int)((threads_per_tile + block - 1) / block); // 3125
    int grid = blocks_per_tile * N_TILES;                                // 25000

    max_agg_kernel<<<grid, block>>>(neighbor_idx, features, out,
                                    n_nodes, blocks_per_tile);
}